// round 1
// baseline (speedup 1.0000x reference)
#include <cuda_runtime.h>
#include <math.h>

// Problem constants
#define B_  4
#define T_  1024
#define D_  2048
#define KV_ 512
#define NH_ 32
#define NKV_ 8
#define HD_ 64
#define MROWS (B_*T_)   // 4096

// Scratch (static device globals; no runtime allocation)
__device__ float g_Q[MROWS * D_];    // rope'd, pre-scaled by 1/8
__device__ float g_K[MROWS * KV_];   // rope'd
__device__ float g_V[MROWS * KV_];
__device__ float g_KN[B_ * NKV_ * T_]; // 0.5*||k||^2 / 8 per key
__device__ float g_Y[MROWS * D_];    // attention output, (b,t,h*hd) layout

// ---------------------------------------------------------------------------
// SGEMM: C[M,N] = A[M,K] @ B[K,N], all row-major, M%128==0, N%128==0, K%16==0
// 128x128 block tile, BK=16, 256 threads, 8x8 microtile per thread.
// ---------------------------------------------------------------------------
__global__ __launch_bounds__(256) void sgemm_kernel(
    const float* __restrict__ A, const float* __restrict__ Bm,
    float* __restrict__ C, int M, int N, int K)
{
    __shared__ float As[16][128];   // transposed A tile: As[k][m]
    __shared__ float Bs[16][128];   // Bs[k][n]

    const int tid = threadIdx.x;
    const int tx = tid & 15;        // 0..15 -> column group
    const int ty = tid >> 4;        // 0..15 -> row group
    const int bx = blockIdx.x, by = blockIdx.y;

    const float* Ab = A + (size_t)by * 128 * K;
    const float* Bb = Bm + (size_t)bx * 128;

    float acc[8][8];
#pragma unroll
    for (int i = 0; i < 8; i++)
#pragma unroll
        for (int j = 0; j < 8; j++) acc[i][j] = 0.f;

    // A-tile load: 128 rows x 16 cols = 512 float4; 2 per thread
    const int lrow0 = tid >> 2;            // 0..63
    const int lrow1 = lrow0 + 64;          // 64..127
    const int lk    = (tid & 3) * 4;       // 0,4,8,12
    // B-tile load: 16 rows x 128 cols = 512 float4; 2 per thread
    const int bk = tid >> 5;               // 0..7
    const int bc = (tid & 31) * 4;         // 0..124

    for (int k0 = 0; k0 < K; k0 += 16) {
        float4 a0 = *(const float4*)(Ab + (size_t)lrow0 * K + k0 + lk);
        float4 a1 = *(const float4*)(Ab + (size_t)lrow1 * K + k0 + lk);
        float4 b0 = *(const float4*)(Bb + (size_t)(k0 + bk) * N + bc);
        float4 b1 = *(const float4*)(Bb + (size_t)(k0 + bk + 8) * N + bc);

        __syncthreads();   // previous iteration's readers done
        As[lk + 0][lrow0] = a0.x; As[lk + 1][lrow0] = a0.y;
        As[lk + 2][lrow0] = a0.z; As[lk + 3][lrow0] = a0.w;
        As[lk + 0][lrow1] = a1.x; As[lk + 1][lrow1] = a1.y;
        As[lk + 2][lrow1] = a1.z; As[lk + 3][lrow1] = a1.w;
        *(float4*)&Bs[bk][bc]     = b0;
        *(float4*)&Bs[bk + 8][bc] = b1;
        __syncthreads();

#pragma unroll
        for (int kk = 0; kk < 16; kk++) {
            float4 ta0 = *(const float4*)&As[kk][ty * 4];
            float4 ta1 = *(const float4*)&As[kk][64 + ty * 4];
            float4 tb0 = *(const float4*)&Bs[kk][tx * 4];
            float4 tb1 = *(const float4*)&Bs[kk][64 + tx * 4];
            float ar[8] = {ta0.x, ta0.y, ta0.z, ta0.w, ta1.x, ta1.y, ta1.z, ta1.w};
            float br[8] = {tb0.x, tb0.y, tb0.z, tb0.w, tb1.x, tb1.y, tb1.z, tb1.w};
#pragma unroll
            for (int i = 0; i < 8; i++)
#pragma unroll
                for (int j = 0; j < 8; j++)
                    acc[i][j] += ar[i] * br[j];
        }
    }

    // writeback
    const int ccol = bx * 128 + tx * 4;
#pragma unroll
    for (int i = 0; i < 8; i++) {
        int r = by * 128 + ((i < 4) ? (ty * 4 + i) : (64 + ty * 4 + (i - 4)));
        float4 v0 = make_float4(acc[i][0], acc[i][1], acc[i][2], acc[i][3]);
        float4 v1 = make_float4(acc[i][4], acc[i][5], acc[i][6], acc[i][7]);
        *(float4*)(C + (size_t)r * N + ccol)      = v0;
        *(float4*)(C + (size_t)r * N + ccol + 64) = v1;
    }
}

// ---------------------------------------------------------------------------
// RoPE for Q (in place), also pre-scales by 1/sqrt(HD)=0.125.
// grid = MROWS, block = NH*32 = 1024. thread = (head, pair-index i in 0..31)
// ---------------------------------------------------------------------------
__global__ void rope_q_kernel()
{
    const int row  = blockIdx.x;         // b*T + t
    const int tpos = row & (T_ - 1);
    const int h = threadIdx.x >> 5;
    const int i = threadIdx.x & 31;

    float inv = 1.0f / powf(10000.0f, (float)i * (1.0f / 32.0f));
    float s, c;
    sincosf((float)tpos * inv, &s, &c);

    float* p = g_Q + (size_t)row * D_ + h * HD_;
    float x1 = p[i], x2 = p[i + 32];
    p[i]      = (x1 * c - x2 * s) * 0.125f;
    p[i + 32] = (x2 * c + x1 * s) * 0.125f;
}

// ---------------------------------------------------------------------------
// RoPE for K (in place) + per-key 0.5*||k||^2/8 into g_KN.
// grid = MROWS, block = NKV*32 = 256. One warp per (row, kv-head).
// ---------------------------------------------------------------------------
__global__ void rope_k_kernel()
{
    const int row  = blockIdx.x;
    const int tpos = row & (T_ - 1);
    const int h = threadIdx.x >> 5;   // 0..7
    const int i = threadIdx.x & 31;

    float inv = 1.0f / powf(10000.0f, (float)i * (1.0f / 32.0f));
    float s, c;
    sincosf((float)tpos * inv, &s, &c);

    float* p = g_K + (size_t)row * KV_ + h * HD_;
    float x1 = p[i], x2 = p[i + 32];
    float o1 = x1 * c - x2 * s;
    float o2 = x2 * c + x1 * s;
    p[i]      = o1;
    p[i + 32] = o2;

    float nsq = o1 * o1 + o2 * o2;
#pragma unroll
    for (int off = 16; off; off >>= 1)
        nsq += __shfl_xor_sync(0xffffffffu, nsq, off);
    if (i == 0) {
        int b = row / T_;
        g_KN[(b * NKV_ + h) * T_ + tpos] = nsq * 0.0625f;  // 0.5/8
    }
}

// ---------------------------------------------------------------------------
// Flash attention (causal, conformal score). One query row per thread.
// grid = (T/128, B*NH), block = 128.
// q already scaled by 1/8; score = q.k - kn[j]; -0.5||q||^2 cancels in softmax.
// Output written in (b, t, h*HD) layout -> directly GEMM-able with Wo.
// ---------------------------------------------------------------------------
__global__ __launch_bounds__(128) void flash_kernel()
{
    const int bh  = blockIdx.y;
    const int b   = bh >> 5;
    const int h   = bh & 31;
    const int kvh = h >> 2;
    const int q0  = blockIdx.x << 7;
    const int tid = threadIdx.x;
    const int qrow = q0 + tid;

    __shared__ float Ks[64][64];
    __shared__ float Vs[64][64];
    __shared__ float kns[64];

    float q[64], acc[64];
    const float* qp = g_Q + (size_t)(b * T_ + qrow) * D_ + h * HD_;
#pragma unroll
    for (int d4 = 0; d4 < 16; d4++) {
        float4 v = ((const float4*)qp)[d4];
        q[4 * d4 + 0] = v.x; q[4 * d4 + 1] = v.y;
        q[4 * d4 + 2] = v.z; q[4 * d4 + 3] = v.w;
    }
#pragma unroll
    for (int d = 0; d < 64; d++) acc[d] = 0.f;

    float m = -1e30f, l = 0.f;

    const int ntiles = (blockIdx.x << 1) + 2;  // keys 0 .. q0+127
    const int r  = tid >> 1;             // 0..63 tile row
    const int ch = (tid & 1) << 5;       // 0 or 32

    for (int kt = 0; kt < ntiles; kt++) {
        const int kbase = kt << 6;
        const float* kp = g_K + (size_t)(b * T_ + kbase + r) * KV_ + kvh * HD_ + ch;
        const float* vp = g_V + (size_t)(b * T_ + kbase + r) * KV_ + kvh * HD_ + ch;

        __syncthreads();   // previous tile fully consumed
#pragma unroll
        for (int u = 0; u < 8; u++)
            ((float4*)&Ks[r][ch])[u] = ((const float4*)kp)[u];
#pragma unroll
        for (int u = 0; u < 8; u++)
            ((float4*)&Vs[r][ch])[u] = ((const float4*)vp)[u];
        if (tid < 64)
            kns[tid] = g_KN[(b * NKV_ + kvh) * T_ + kbase + tid];
        __syncthreads();

        int jlim = qrow - kbase + 1;     // # valid keys in this tile for me
        if (jlim > 64) jlim = 64;

        for (int jj = 0; jj < jlim; jj += 8) {
            float s[8];
#pragma unroll
            for (int jk = 0; jk < 8; jk++) s[jk] = -kns[jj + jk];
#pragma unroll
            for (int d4 = 0; d4 < 16; d4++) {
                const float qa = q[4 * d4 + 0], qb = q[4 * d4 + 1];
                const float qc = q[4 * d4 + 2], qd = q[4 * d4 + 3];
#pragma unroll
                for (int jk = 0; jk < 8; jk++) {
                    float4 kk = *(const float4*)&Ks[jj + jk][d4 << 2];
                    s[jk] += qa * kk.x + qb * kk.y + qc * kk.z + qd * kk.w;
                }
            }
            // causal mask + chunk max
            float cm = -1e30f;
#pragma unroll
            for (int jk = 0; jk < 8; jk++) {
                if (jj + jk >= jlim) s[jk] = -1e30f;
                cm = fmaxf(cm, s[jk]);
            }
            float mnew = fmaxf(m, cm);
            float corr = __expf(m - mnew);
            float p[8];
            float ps = 0.f;
#pragma unroll
            for (int jk = 0; jk < 8; jk++) {
                p[jk] = __expf(s[jk] - mnew);   // masked -> exp(-1e30) = 0
                ps += p[jk];
            }
            l = l * corr + ps;
#pragma unroll
            for (int dd = 0; dd < 64; dd += 4) {
                float a0 = acc[dd + 0] * corr;
                float a1 = acc[dd + 1] * corr;
                float a2 = acc[dd + 2] * corr;
                float a3 = acc[dd + 3] * corr;
#pragma unroll
                for (int jk = 0; jk < 8; jk++) {
                    float4 vv = *(const float4*)&Vs[jj + jk][dd];
                    a0 += p[jk] * vv.x; a1 += p[jk] * vv.y;
                    a2 += p[jk] * vv.z; a3 += p[jk] * vv.w;
                }
                acc[dd + 0] = a0; acc[dd + 1] = a1;
                acc[dd + 2] = a2; acc[dd + 3] = a3;
            }
            m = mnew;
        }
    }

    float invl = 1.0f / l;
    float* yp = g_Y + (size_t)(b * T_ + qrow) * D_ + h * HD_;
#pragma unroll
    for (int d4 = 0; d4 < 16; d4++) {
        float4 v;
        v.x = acc[4 * d4 + 0] * invl;
        v.y = acc[4 * d4 + 1] * invl;
        v.z = acc[4 * d4 + 2] * invl;
        v.w = acc[4 * d4 + 3] * invl;
        ((float4*)yp)[d4] = v;
    }
}

// ---------------------------------------------------------------------------
extern "C" void kernel_launch(void* const* d_in, const int* in_sizes, int n_in,
                              void* d_out, int out_size)
{
    const float* x  = (const float*)d_in[0];
    const float* Wq = (const float*)d_in[1];
    const float* Wk = (const float*)d_in[2];
    const float* Wv = (const float*)d_in[3];
    const float* Wo = (const float*)d_in[4];
    float* out = (float*)d_out;

    float *Q, *K, *V, *Y;
    cudaGetSymbolAddress((void**)&Q, g_Q);
    cudaGetSymbolAddress((void**)&K, g_K);
    cudaGetSymbolAddress((void**)&V, g_V);
    cudaGetSymbolAddress((void**)&Y, g_Y);

    // Projections
    sgemm_kernel<<<dim3(D_ / 128, MROWS / 128), 256>>>(x, Wq, Q, MROWS, D_, D_);
    sgemm_kernel<<<dim3(KV_ / 128, MROWS / 128), 256>>>(x, Wk, K, MROWS, KV_, D_);
    sgemm_kernel<<<dim3(KV_ / 128, MROWS / 128), 256>>>(x, Wv, V, MROWS, KV_, D_);

    // RoPE (+ q pre-scale, + k norm precompute)
    rope_q_kernel<<<MROWS, NH_ * 32>>>();
    rope_k_kernel<<<MROWS, NKV_ * 32>>>();

    // Attention
    flash_kernel<<<dim3(T_ / 128, B_ * NH_), 128>>>();

    // Output projection
    sgemm_kernel<<<dim3(D_ / 128, MROWS / 128), 256>>>(Y, Wo, out, MROWS, D_, D_);
}

// round 2
// speedup vs baseline: 1.5398x; 1.5398x over previous
#include <cuda_runtime.h>
#include <math.h>
#include <stdint.h>

// Problem constants
#define B_  4
#define T_  1024
#define D_  2048
#define KV_ 512
#define NH_ 32
#define NKV_ 8
#define HD_ 64
#define MROWS (B_*T_)   // 4096

// Scratch (static device globals; no runtime allocation)
__device__ float g_Q[MROWS * D_];    // rope'd, pre-scaled by 1/8
__device__ float g_K[MROWS * KV_];   // rope'd
__device__ float g_V[MROWS * KV_];
__device__ float g_KN[B_ * NKV_ * T_]; // 0.5*||k||^2 / 8 per key
__device__ float g_Y[MROWS * D_];    // attention output, (b,t,h*hd) layout

// ---------------------------------------------------------------------------
// tf32 helpers
// ---------------------------------------------------------------------------
__device__ __forceinline__ uint32_t f2tf32(float x) {
    uint32_t r;
    asm("cvt.rna.tf32.f32 %0, %1;" : "=r"(r) : "f"(x));
    return r;
}

__device__ __forceinline__ void mma_tf32(float c[4],
    uint32_t a0, uint32_t a1, uint32_t a2, uint32_t a3,
    uint32_t b0, uint32_t b1)
{
    asm volatile(
        "mma.sync.aligned.m16n8k8.row.col.f32.tf32.tf32.f32 "
        "{%0,%1,%2,%3}, {%4,%5,%6,%7}, {%8,%9}, {%0,%1,%2,%3};"
        : "+f"(c[0]), "+f"(c[1]), "+f"(c[2]), "+f"(c[3])
        : "r"(a0), "r"(a1), "r"(a2), "r"(a3), "r"(b0), "r"(b1));
}

// ---------------------------------------------------------------------------
// tf32 tensor-core GEMM: C[M,N] = A[M,K] @ B[K,N], row-major.
// M%128==0, N%128==0, K%32==0.
// Block: 256 threads (8 warps as 2Mx4N), tile 128x128x32.
// Warp tile 64x32, built from m16n8k8 mma (4 M-frags x 4 N-frags x 4 k-steps).
// As[128][36]: A-frag LDS bank = (4*group+tig) -> bijective, conflict-free.
// Bs[32][136]: B-frag LDS bank = (8*tig+group) -> bijective, conflict-free.
// ---------------------------------------------------------------------------
__global__ __launch_bounds__(256) void gemm_tf32_kernel(
    const float* __restrict__ A, const float* __restrict__ Bm,
    float* __restrict__ C, int M, int N, int K)
{
    __shared__ uint32_t As[128][36];
    __shared__ uint32_t Bs[32][136];

    const int tid  = threadIdx.x;
    const int lane = tid & 31;
    const int wid  = tid >> 5;
    const int g    = lane >> 2;   // group 0..7
    const int t    = lane & 3;    // thread-in-group 0..3
    const int wm   = (wid & 1) * 64;   // warp M base in tile
    const int wn   = (wid >> 1) * 32;  // warp N base in tile
    const int bx = blockIdx.x, by = blockIdx.y;

    float acc[4][4][4];
#pragma unroll
    for (int mi = 0; mi < 4; mi++)
#pragma unroll
        for (int nj = 0; nj < 4; nj++)
#pragma unroll
            for (int e = 0; e < 4; e++) acc[mi][nj][e] = 0.f;

    const float* Ab = A + (size_t)(by * 128) * K;
    const float* Bb = Bm + (size_t)bx * 128;

    // global->smem assignments: 16 elems (4 float4) each for A and B tiles
    const int arow = tid >> 1;            // 0..127
    const int acol = (tid & 1) * 16;      // 0 or 16
    const int brow = tid >> 3;            // 0..31
    const int bcol = (tid & 7) * 16;      // 0..112

    for (int k0 = 0; k0 < K; k0 += 32) {
        float4 av[4], bv[4];
#pragma unroll
        for (int u = 0; u < 4; u++)
            av[u] = *(const float4*)(Ab + (size_t)arow * K + k0 + acol + 4 * u);
#pragma unroll
        for (int u = 0; u < 4; u++)
            bv[u] = *(const float4*)(Bb + (size_t)(k0 + brow) * N + bcol + 4 * u);

        __syncthreads();   // previous tile fully consumed
#pragma unroll
        for (int u = 0; u < 4; u++) {
            uint32_t* p = &As[arow][acol + 4 * u];
            p[0] = f2tf32(av[u].x); p[1] = f2tf32(av[u].y);
            p[2] = f2tf32(av[u].z); p[3] = f2tf32(av[u].w);
        }
#pragma unroll
        for (int u = 0; u < 4; u++) {
            uint32_t* p = &Bs[brow][bcol + 4 * u];
            p[0] = f2tf32(bv[u].x); p[1] = f2tf32(bv[u].y);
            p[2] = f2tf32(bv[u].z); p[3] = f2tf32(bv[u].w);
        }
        __syncthreads();

#pragma unroll
        for (int ks = 0; ks < 4; ks++) {
            const int kc = ks * 8;
            uint32_t a[4][4];
#pragma unroll
            for (int mi = 0; mi < 4; mi++) {
                const int r0 = wm + mi * 16 + g;
                a[mi][0] = As[r0][kc + t];
                a[mi][1] = As[r0 + 8][kc + t];
                a[mi][2] = As[r0][kc + t + 4];
                a[mi][3] = As[r0 + 8][kc + t + 4];
            }
            uint32_t b[4][2];
#pragma unroll
            for (int nj = 0; nj < 4; nj++) {
                const int c0 = wn + nj * 8 + g;
                b[nj][0] = Bs[kc + t][c0];
                b[nj][1] = Bs[kc + t + 4][c0];
            }
#pragma unroll
            for (int mi = 0; mi < 4; mi++)
#pragma unroll
                for (int nj = 0; nj < 4; nj++)
                    mma_tf32(acc[mi][nj], a[mi][0], a[mi][1], a[mi][2], a[mi][3],
                             b[nj][0], b[nj][1]);
        }
    }

    // writeback: c0,c1 at (row g, cols 2t..2t+1); c2,c3 at row g+8
#pragma unroll
    for (int mi = 0; mi < 4; mi++) {
        const int r0 = by * 128 + wm + mi * 16 + g;
#pragma unroll
        for (int nj = 0; nj < 4; nj++) {
            const int col = bx * 128 + wn + nj * 8 + 2 * t;
            float2 v0 = make_float2(acc[mi][nj][0], acc[mi][nj][1]);
            float2 v1 = make_float2(acc[mi][nj][2], acc[mi][nj][3]);
            *(float2*)(C + (size_t)r0 * N + col)       = v0;
            *(float2*)(C + (size_t)(r0 + 8) * N + col) = v1;
        }
    }
}

// ---------------------------------------------------------------------------
// RoPE for Q (in place), also pre-scales by 1/sqrt(HD)=0.125.
// grid = MROWS, block = NH*32 = 1024. thread = (head, pair-index i in 0..31)
// ---------------------------------------------------------------------------
__global__ void rope_q_kernel()
{
    const int row  = blockIdx.x;         // b*T + t
    const int tpos = row & (T_ - 1);
    const int h = threadIdx.x >> 5;
    const int i = threadIdx.x & 31;

    float inv = 1.0f / powf(10000.0f, (float)i * (1.0f / 32.0f));
    float s, c;
    sincosf((float)tpos * inv, &s, &c);

    float* p = g_Q + (size_t)row * D_ + h * HD_;
    float x1 = p[i], x2 = p[i + 32];
    p[i]      = (x1 * c - x2 * s) * 0.125f;
    p[i + 32] = (x2 * c + x1 * s) * 0.125f;
}

// ---------------------------------------------------------------------------
// RoPE for K (in place) + per-key 0.5*||k||^2/8 into g_KN.
// grid = MROWS, block = NKV*32 = 256. One warp per (row, kv-head).
// ---------------------------------------------------------------------------
__global__ void rope_k_kernel()
{
    const int row  = blockIdx.x;
    const int tpos = row & (T_ - 1);
    const int h = threadIdx.x >> 5;   // 0..7
    const int i = threadIdx.x & 31;

    float inv = 1.0f / powf(10000.0f, (float)i * (1.0f / 32.0f));
    float s, c;
    sincosf((float)tpos * inv, &s, &c);

    float* p = g_K + (size_t)row * KV_ + h * HD_;
    float x1 = p[i], x2 = p[i + 32];
    float o1 = x1 * c - x2 * s;
    float o2 = x2 * c + x1 * s;
    p[i]      = o1;
    p[i + 32] = o2;

    float nsq = o1 * o1 + o2 * o2;
#pragma unroll
    for (int off = 16; off; off >>= 1)
        nsq += __shfl_xor_sync(0xffffffffu, nsq, off);
    if (i == 0) {
        int b = row / T_;
        g_KN[(b * NKV_ + h) * T_ + tpos] = nsq * 0.0625f;  // 0.5/8
    }
}

// ---------------------------------------------------------------------------
// Flash attention (causal, conformal score). One query row per thread.
// grid = (T/128, B*NH), block = 128.
// q already scaled by 1/8; score = q.k - kn[j]; -0.5||q||^2 cancels in softmax.
// Output written in (b, t, h*HD) layout -> directly GEMM-able with Wo.
// ---------------------------------------------------------------------------
__global__ __launch_bounds__(128) void flash_kernel()
{
    const int bh  = blockIdx.y;
    const int b   = bh >> 5;
    const int h   = bh & 31;
    const int kvh = h >> 2;
    const int q0  = blockIdx.x << 7;
    const int tid = threadIdx.x;
    const int qrow = q0 + tid;

    __shared__ float Ks[64][64];
    __shared__ float Vs[64][64];
    __shared__ float kns[64];

    float q[64], acc[64];
    const float* qp = g_Q + (size_t)(b * T_ + qrow) * D_ + h * HD_;
#pragma unroll
    for (int d4 = 0; d4 < 16; d4++) {
        float4 v = ((const float4*)qp)[d4];
        q[4 * d4 + 0] = v.x; q[4 * d4 + 1] = v.y;
        q[4 * d4 + 2] = v.z; q[4 * d4 + 3] = v.w;
    }
#pragma unroll
    for (int d = 0; d < 64; d++) acc[d] = 0.f;

    float m = -1e30f, l = 0.f;

    const int ntiles = (blockIdx.x << 1) + 2;  // keys 0 .. q0+127
    const int r  = tid >> 1;             // 0..63 tile row
    const int ch = (tid & 1) << 5;       // 0 or 32

    for (int kt = 0; kt < ntiles; kt++) {
        const int kbase = kt << 6;
        const float* kp = g_K + (size_t)(b * T_ + kbase + r) * KV_ + kvh * HD_ + ch;
        const float* vp = g_V + (size_t)(b * T_ + kbase + r) * KV_ + kvh * HD_ + ch;

        __syncthreads();   // previous tile fully consumed
#pragma unroll
        for (int u = 0; u < 8; u++)
            ((float4*)&Ks[r][ch])[u] = ((const float4*)kp)[u];
#pragma unroll
        for (int u = 0; u < 8; u++)
            ((float4*)&Vs[r][ch])[u] = ((const float4*)vp)[u];
        if (tid < 64)
            kns[tid] = g_KN[(b * NKV_ + kvh) * T_ + kbase + tid];
        __syncthreads();

        int jlim = qrow - kbase + 1;     // # valid keys in this tile for me
        if (jlim > 64) jlim = 64;

        for (int jj = 0; jj < jlim; jj += 8) {
            float s[8];
#pragma unroll
            for (int jk = 0; jk < 8; jk++) s[jk] = -kns[jj + jk];
#pragma unroll
            for (int d4 = 0; d4 < 16; d4++) {
                const float qa = q[4 * d4 + 0], qb = q[4 * d4 + 1];
                const float qc = q[4 * d4 + 2], qd = q[4 * d4 + 3];
#pragma unroll
                for (int jk = 0; jk < 8; jk++) {
                    float4 kk = *(const float4*)&Ks[jj + jk][d4 << 2];
                    s[jk] += qa * kk.x + qb * kk.y + qc * kk.z + qd * kk.w;
                }
            }
            // causal mask + chunk max
            float cm = -1e30f;
#pragma unroll
            for (int jk = 0; jk < 8; jk++) {
                if (jj + jk >= jlim) s[jk] = -1e30f;
                cm = fmaxf(cm, s[jk]);
            }
            float mnew = fmaxf(m, cm);
            float corr = __expf(m - mnew);
            float p[8];
            float ps = 0.f;
#pragma unroll
            for (int jk = 0; jk < 8; jk++) {
                p[jk] = __expf(s[jk] - mnew);   // masked -> exp(-1e30) = 0
                ps += p[jk];
            }
            l = l * corr + ps;
#pragma unroll
            for (int dd = 0; dd < 64; dd += 4) {
                float a0 = acc[dd + 0] * corr;
                float a1 = acc[dd + 1] * corr;
                float a2 = acc[dd + 2] * corr;
                float a3 = acc[dd + 3] * corr;
#pragma unroll
                for (int jk = 0; jk < 8; jk++) {
                    float4 vv = *(const float4*)&Vs[jj + jk][dd];
                    a0 += p[jk] * vv.x; a1 += p[jk] * vv.y;
                    a2 += p[jk] * vv.z; a3 += p[jk] * vv.w;
                }
                acc[dd + 0] = a0; acc[dd + 1] = a1;
                acc[dd + 2] = a2; acc[dd + 3] = a3;
            }
            m = mnew;
        }
    }

    float invl = 1.0f / l;
    float* yp = g_Y + (size_t)(b * T_ + qrow) * D_ + h * HD_;
#pragma unroll
    for (int d4 = 0; d4 < 16; d4++) {
        float4 v;
        v.x = acc[4 * d4 + 0] * invl;
        v.y = acc[4 * d4 + 1] * invl;
        v.z = acc[4 * d4 + 2] * invl;
        v.w = acc[4 * d4 + 3] * invl;
        ((float4*)yp)[d4] = v;
    }
}

// ---------------------------------------------------------------------------
extern "C" void kernel_launch(void* const* d_in, const int* in_sizes, int n_in,
                              void* d_out, int out_size)
{
    const float* x  = (const float*)d_in[0];
    const float* Wq = (const float*)d_in[1];
    const float* Wk = (const float*)d_in[2];
    const float* Wv = (const float*)d_in[3];
    const float* Wo = (const float*)d_in[4];
    float* out = (float*)d_out;

    float *Q, *K, *V, *Y;
    cudaGetSymbolAddress((void**)&Q, g_Q);
    cudaGetSymbolAddress((void**)&K, g_K);
    cudaGetSymbolAddress((void**)&V, g_V);
    cudaGetSymbolAddress((void**)&Y, g_Y);

    // Projections (tf32 tensor cores)
    gemm_tf32_kernel<<<dim3(D_ / 128, MROWS / 128), 256>>>(x, Wq, Q, MROWS, D_, D_);
    gemm_tf32_kernel<<<dim3(KV_ / 128, MROWS / 128), 256>>>(x, Wk, K, MROWS, KV_, D_);
    gemm_tf32_kernel<<<dim3(KV_ / 128, MROWS / 128), 256>>>(x, Wv, V, MROWS, KV_, D_);

    // RoPE (+ q pre-scale, + k norm precompute)
    rope_q_kernel<<<MROWS, NH_ * 32>>>();
    rope_k_kernel<<<MROWS, NKV_ * 32>>>();

    // Attention
    flash_kernel<<<dim3(T_ / 128, B_ * NH_), 128>>>();

    // Output projection
    gemm_tf32_kernel<<<dim3(D_ / 128, MROWS / 128), 256>>>(Y, Wo, out, MROWS, D_, D_);
}

// round 3
// speedup vs baseline: 2.5751x; 1.6724x over previous
#include <cuda_runtime.h>
#include <math.h>
#include <stdint.h>

// Problem constants
#define B_  4
#define T_  1024
#define D_  2048
#define KV_ 512
#define NH_ 32
#define NKV_ 8
#define HD_ 64
#define MROWS (B_*T_)   // 4096

// Scratch (static device globals; no runtime allocation)
__device__ float g_Q[MROWS * D_];     // rope'd, pre-scaled by 1/8, tf32-rounded
__device__ float g_K[MROWS * KV_];    // rope'd, tf32-rounded
__device__ float g_V[MROWS * KV_];    // tf32-rounded
__device__ float g_KN[B_ * NKV_ * T_];// 0.5*||k||^2 / 8 per key
__device__ float g_Y[MROWS * D_];     // attention out, (b,t,h*hd), tf32-rounded
// tf32-rounded copies of inputs (GEMM operands, raw cp.async-able)
__device__ float g_xr[MROWS * D_];
__device__ float g_Wqr[D_ * D_];
__device__ float g_Wkr[D_ * KV_];
__device__ float g_Wvr[D_ * KV_];
__device__ float g_Wor[D_ * D_];

// ---------------------------------------------------------------------------
// helpers
// ---------------------------------------------------------------------------
__device__ __forceinline__ uint32_t f2tf32(float x) {
    uint32_t r;
    asm("cvt.rna.tf32.f32 %0, %1;" : "=r"(r) : "f"(x));
    return r;
}
__device__ __forceinline__ float tf32r(float x) { return __uint_as_float(f2tf32(x)); }

__device__ __forceinline__ void mma_tf32(float c[4],
    uint32_t a0, uint32_t a1, uint32_t a2, uint32_t a3,
    uint32_t b0, uint32_t b1)
{
    asm volatile(
        "mma.sync.aligned.m16n8k8.row.col.f32.tf32.tf32.f32 "
        "{%0,%1,%2,%3}, {%4,%5,%6,%7}, {%8,%9}, {%0,%1,%2,%3};"
        : "+f"(c[0]), "+f"(c[1]), "+f"(c[2]), "+f"(c[3])
        : "r"(a0), "r"(a1), "r"(a2), "r"(a3), "r"(b0), "r"(b1));
}

__device__ __forceinline__ void cp_async16(uint32_t smem, const void* gmem) {
    asm volatile("cp.async.cg.shared.global [%0], [%1], 16;" :: "r"(smem), "l"(gmem));
}
__device__ __forceinline__ void cp_commit() {
    asm volatile("cp.async.commit_group;");
}
template<int N> __device__ __forceinline__ void cp_wait() {
    asm volatile("cp.async.wait_group %0;" :: "n"(N));
}
__device__ __forceinline__ uint32_t smem_u32(const void* p) {
    return (uint32_t)__cvta_generic_to_shared(p);
}

// ---------------------------------------------------------------------------
// Elementwise tf32 rounding pass (float4 per thread)
// ---------------------------------------------------------------------------
__global__ void round4_kernel(const float* __restrict__ s, float* __restrict__ d, int n4)
{
    int i = blockIdx.x * blockDim.x + threadIdx.x;
    if (i < n4) {
        float4 v = ((const float4*)s)[i];
        v.x = tf32r(v.x); v.y = tf32r(v.y); v.z = tf32r(v.z); v.w = tf32r(v.w);
        ((float4*)d)[i] = v;
    }
}

// ---------------------------------------------------------------------------
// tf32 GEMM, cp.async double-buffered. C[M,N] = A@B, row-major.
// Inputs MUST be pre-rounded to tf32 bit patterns.
// Tile 128x128xBK16, 256 thr (8 warps 2Mx4N), warp 64x32, m16n8k8.
// As[128][20]: frag banks (20g+t)%32 all distinct. Bs[16][136]: (8t+g) distinct.
// ---------------------------------------------------------------------------
__global__ __launch_bounds__(256) void gemm_tf32_db(
    const float* __restrict__ A, const float* __restrict__ Bm,
    float* __restrict__ C, int M, int N, int K)
{
    __shared__ float As[2][128][20];
    __shared__ float Bs[2][16][136];

    const int tid  = threadIdx.x;
    const int lane = tid & 31;
    const int wid  = tid >> 5;
    const int g    = lane >> 2;
    const int t    = lane & 3;
    const int wm   = (wid & 1) * 64;
    const int wn   = (wid >> 1) * 32;
    const int bx = blockIdx.x, by = blockIdx.y;

    float acc[4][4][4];
#pragma unroll
    for (int mi = 0; mi < 4; mi++)
#pragma unroll
        for (int nj = 0; nj < 4; nj++)
#pragma unroll
            for (int e = 0; e < 4; e++) acc[mi][nj][e] = 0.f;

    const float* Ab = A + (size_t)(by * 128) * K;
    const float* Bb = Bm + (size_t)bx * 128;

    const int ar = tid >> 1, ac = (tid & 1) * 8;   // A: 128 rows x 16k, 8 floats/thr
    const int br = tid >> 4, bc = (tid & 15) * 8;  // B: 16 rows x 128n, 8 floats/thr

    const int niter = K >> 4;

    // prologue: tile 0 -> buf 0
    {
        cp_async16(smem_u32(&As[0][ar][ac]),     Ab + (size_t)ar * K + ac);
        cp_async16(smem_u32(&As[0][ar][ac + 4]), Ab + (size_t)ar * K + ac + 4);
        cp_async16(smem_u32(&Bs[0][br][bc]),     Bb + (size_t)br * N + bc);
        cp_async16(smem_u32(&Bs[0][br][bc + 4]), Bb + (size_t)br * N + bc + 4);
        cp_commit();
    }

    for (int it = 0; it < niter; it++) {
        const int cb = it & 1;
        if (it + 1 < niter) {
            const int k0 = (it + 1) << 4;
            const int nb = cb ^ 1;
            cp_async16(smem_u32(&As[nb][ar][ac]),     Ab + (size_t)ar * K + k0 + ac);
            cp_async16(smem_u32(&As[nb][ar][ac + 4]), Ab + (size_t)ar * K + k0 + ac + 4);
            cp_async16(smem_u32(&Bs[nb][br][bc]),     Bb + (size_t)(k0 + br) * N + bc);
            cp_async16(smem_u32(&Bs[nb][br][bc + 4]), Bb + (size_t)(k0 + br) * N + bc + 4);
            cp_commit();
            cp_wait<1>();
        } else {
            cp_wait<0>();
        }
        __syncthreads();

#pragma unroll
        for (int ks = 0; ks < 2; ks++) {
            const int kc = ks * 8;
            uint32_t a[4][4];
#pragma unroll
            for (int mi = 0; mi < 4; mi++) {
                const int r0 = wm + mi * 16 + g;
                a[mi][0] = __float_as_uint(As[cb][r0][kc + t]);
                a[mi][1] = __float_as_uint(As[cb][r0 + 8][kc + t]);
                a[mi][2] = __float_as_uint(As[cb][r0][kc + t + 4]);
                a[mi][3] = __float_as_uint(As[cb][r0 + 8][kc + t + 4]);
            }
            uint32_t b[4][2];
#pragma unroll
            for (int nj = 0; nj < 4; nj++) {
                const int c0 = wn + nj * 8 + g;
                b[nj][0] = __float_as_uint(Bs[cb][kc + t][c0]);
                b[nj][1] = __float_as_uint(Bs[cb][kc + t + 4][c0]);
            }
#pragma unroll
            for (int mi = 0; mi < 4; mi++)
#pragma unroll
                for (int nj = 0; nj < 4; nj++)
                    mma_tf32(acc[mi][nj], a[mi][0], a[mi][1], a[mi][2], a[mi][3],
                             b[nj][0], b[nj][1]);
        }
        __syncthreads();
    }

#pragma unroll
    for (int mi = 0; mi < 4; mi++) {
        const int r0 = by * 128 + wm + mi * 16 + g;
#pragma unroll
        for (int nj = 0; nj < 4; nj++) {
            const int col = bx * 128 + wn + nj * 8 + 2 * t;
            *(float2*)(C + (size_t)r0 * N + col)       = make_float2(acc[mi][nj][0], acc[mi][nj][1]);
            *(float2*)(C + (size_t)(r0 + 8) * N + col) = make_float2(acc[mi][nj][2], acc[mi][nj][3]);
        }
    }
}

// ---------------------------------------------------------------------------
// RoPE for Q (in place): scale by 0.125, round to tf32.
// ---------------------------------------------------------------------------
__global__ void rope_q_kernel()
{
    const int row  = blockIdx.x;
    const int tpos = row & (T_ - 1);
    const int h = threadIdx.x >> 5;
    const int i = threadIdx.x & 31;

    float inv = 1.0f / powf(10000.0f, (float)i * (1.0f / 32.0f));
    float s, c;
    sincosf((float)tpos * inv, &s, &c);

    float* p = g_Q + (size_t)row * D_ + h * HD_;
    float x1 = p[i], x2 = p[i + 32];
    p[i]      = tf32r((x1 * c - x2 * s) * 0.125f);
    p[i + 32] = tf32r((x2 * c + x1 * s) * 0.125f);
}

// ---------------------------------------------------------------------------
// RoPE for K (in place, rounded) + kn from ROUNDED k + round V row.
// grid = MROWS, block = 256 (8 warps: one per kv head).
// ---------------------------------------------------------------------------
__global__ void rope_k_kernel()
{
    const int row  = blockIdx.x;
    const int tpos = row & (T_ - 1);
    const int h = threadIdx.x >> 5;
    const int i = threadIdx.x & 31;

    float inv = 1.0f / powf(10000.0f, (float)i * (1.0f / 32.0f));
    float s, c;
    sincosf((float)tpos * inv, &s, &c);

    float* p = g_K + (size_t)row * KV_ + h * HD_;
    float x1 = p[i], x2 = p[i + 32];
    float o1 = tf32r(x1 * c - x2 * s);
    float o2 = tf32r(x2 * c + x1 * s);
    p[i]      = o1;
    p[i + 32] = o2;

    float nsq = o1 * o1 + o2 * o2;
#pragma unroll
    for (int off = 16; off; off >>= 1)
        nsq += __shfl_xor_sync(0xffffffffu, nsq, off);
    if (i == 0) {
        int bb = row / T_;
        g_KN[(bb * NKV_ + h) * T_ + tpos] = nsq * 0.0625f;  // 0.5/8
    }

    // round V row (512 floats, 256 threads -> 2 each)
    float* vp = g_V + (size_t)row * KV_;
    int j = threadIdx.x;
    vp[j]       = tf32r(vp[j]);
    vp[j + 256] = tf32r(vp[j + 256]);
}

// ---------------------------------------------------------------------------
// Flash attention via tf32 mma. Block = 128 thr (4 warps), 64 q-rows, one (b,h).
// grid = (T/64, B*NH); heavy blocks (long causal windows) scheduled first.
// score = q~.k~ - kn (q pre-scaled 1/8; -0.5||q||^2 cancels in softmax).
// Ks stride 68: S-frag banks (4g+t) distinct. Vs stride 72: (8t+g) distinct.
// ---------------------------------------------------------------------------
__global__ __launch_bounds__(128) void flash_mma_kernel()
{
    __shared__ float Ks[64][68];
    __shared__ float Vs[64][72];
    __shared__ float kns[64];

    const int bh  = blockIdx.y;
    const int bb  = bh >> 5;
    const int h   = bh & 31;
    const int kvh = h >> 2;
    const int qb  = gridDim.x - 1 - blockIdx.x;   // heavy first
    const int q0  = qb << 6;
    const int tid = threadIdx.x;
    const int w   = tid >> 5;
    const int lane = tid & 31;
    const int g   = lane >> 2;
    const int t   = lane & 3;

    // ---- stage Q tile (64x64) into Ks, extract A-fragments into regs ----
    {
        const int r = tid >> 1, ch = (tid & 1) << 5;
        const float* qp = g_Q + (size_t)(bb * T_ + q0 + r) * D_ + h * HD_ + ch;
#pragma unroll
        for (int u = 0; u < 8; u++)
            *(float4*)&Ks[r][ch + 4 * u] = ((const float4*)qp)[u];
    }
    __syncthreads();

    uint32_t aq[8][4];
    const int qr = w * 16 + g;
#pragma unroll
    for (int ks = 0; ks < 8; ks++) {
        aq[ks][0] = __float_as_uint(Ks[qr][ks * 8 + t]);
        aq[ks][1] = __float_as_uint(Ks[qr + 8][ks * 8 + t]);
        aq[ks][2] = __float_as_uint(Ks[qr][ks * 8 + t + 4]);
        aq[ks][3] = __float_as_uint(Ks[qr + 8][ks * 8 + t + 4]);
    }
    __syncthreads();

    float oa[8][4];
#pragma unroll
    for (int nd = 0; nd < 8; nd++)
#pragma unroll
        for (int e = 0; e < 4; e++) oa[nd][e] = 0.f;
    float m0 = -1e30f, m1 = -1e30f, l0 = 0.f, l1 = 0.f;

    const int ntiles = qb + 1;
    const int lr = tid >> 1, lch = (tid & 1) << 5;

    for (int kt = 0; kt < ntiles; kt++) {
        const int kbase = kt << 6;
        const float* kp = g_K + (size_t)(bb * T_ + kbase + lr) * KV_ + kvh * HD_ + lch;
        const float* vp = g_V + (size_t)(bb * T_ + kbase + lr) * KV_ + kvh * HD_ + lch;

        __syncthreads();
#pragma unroll
        for (int u = 0; u < 8; u++)
            *(float4*)&Ks[lr][lch + 4 * u] = ((const float4*)kp)[u];
#pragma unroll
        for (int u = 0; u < 8; u++)
            *(float4*)&Vs[lr][lch + 4 * u] = ((const float4*)vp)[u];
        if (tid < 64)
            kns[tid] = g_KN[(bb * NKV_ + kvh) * T_ + kbase + tid];
        __syncthreads();

        // ---- S = Q~ K~^T (16 q-rows x 64 keys per warp) ----
        float sc[8][4];
#pragma unroll
        for (int nj = 0; nj < 8; nj++)
#pragma unroll
            for (int e = 0; e < 4; e++) sc[nj][e] = 0.f;
#pragma unroll
        for (int ks = 0; ks < 8; ks++) {
#pragma unroll
            for (int nj = 0; nj < 8; nj++) {
                uint32_t b0 = __float_as_uint(Ks[nj * 8 + g][ks * 8 + t]);
                uint32_t b1 = __float_as_uint(Ks[nj * 8 + g][ks * 8 + t + 4]);
                mma_tf32(sc[nj], aq[ks][0], aq[ks][1], aq[ks][2], aq[ks][3], b0, b1);
            }
        }

        // ---- conformal term + causal mask + row maxes ----
        float mr0 = -1e30f, mr1 = -1e30f;
        const bool diag = (kt == qb);
#pragma unroll
        for (int nj = 0; nj < 8; nj++) {
            const int c0 = nj * 8 + 2 * t, c1 = c0 + 1;
            float kn0 = kns[c0], kn1 = kns[c1];
            sc[nj][0] -= kn0; sc[nj][1] -= kn1;
            sc[nj][2] -= kn0; sc[nj][3] -= kn1;
            if (diag) {
                const int r0 = w * 16 + g, r1 = r0 + 8;
                if (c0 > r0) sc[nj][0] = -1e30f;
                if (c1 > r0) sc[nj][1] = -1e30f;
                if (c0 > r1) sc[nj][2] = -1e30f;
                if (c1 > r1) sc[nj][3] = -1e30f;
            }
            mr0 = fmaxf(mr0, fmaxf(sc[nj][0], sc[nj][1]));
            mr1 = fmaxf(mr1, fmaxf(sc[nj][2], sc[nj][3]));
        }
        mr0 = fmaxf(mr0, __shfl_xor_sync(0xffffffffu, mr0, 1));
        mr0 = fmaxf(mr0, __shfl_xor_sync(0xffffffffu, mr0, 2));
        mr1 = fmaxf(mr1, __shfl_xor_sync(0xffffffffu, mr1, 1));
        mr1 = fmaxf(mr1, __shfl_xor_sync(0xffffffffu, mr1, 2));

        const float mn0 = fmaxf(m0, mr0), mn1 = fmaxf(m1, mr1);
        const float cor0 = __expf(m0 - mn0), cor1 = __expf(m1 - mn1);
        m0 = mn0; m1 = mn1;

        // ---- P = exp(S - m), row sums ----
        float ps0 = 0.f, ps1 = 0.f;
#pragma unroll
        for (int nj = 0; nj < 8; nj++) {
            sc[nj][0] = __expf(sc[nj][0] - mn0);
            sc[nj][1] = __expf(sc[nj][1] - mn0);
            sc[nj][2] = __expf(sc[nj][2] - mn1);
            sc[nj][3] = __expf(sc[nj][3] - mn1);
            ps0 += sc[nj][0] + sc[nj][1];
            ps1 += sc[nj][2] + sc[nj][3];
        }
        ps0 += __shfl_xor_sync(0xffffffffu, ps0, 1);
        ps0 += __shfl_xor_sync(0xffffffffu, ps0, 2);
        ps1 += __shfl_xor_sync(0xffffffffu, ps1, 1);
        ps1 += __shfl_xor_sync(0xffffffffu, ps1, 2);
        l0 = l0 * cor0 + ps0;
        l1 = l1 * cor1 + ps1;

        // ---- rescale O ----
#pragma unroll
        for (int nd = 0; nd < 8; nd++) {
            oa[nd][0] *= cor0; oa[nd][1] *= cor0;
            oa[nd][2] *= cor1; oa[nd][3] *= cor1;
        }

        // ---- O += P V : relayout P C-frag -> A-frag via shuffles ----
        const int s0 = (lane & ~3) | (t >> 1);
        const int s1 = s0 + 2;
        const bool odd = (t & 1);
#pragma unroll
        for (int ks = 0; ks < 8; ks++) {
            float p0 = sc[ks][0], p1 = sc[ks][1], p2 = sc[ks][2], p3 = sc[ks][3];
            float x0 = __shfl_sync(0xffffffffu, p0, s0);
            float x1 = __shfl_sync(0xffffffffu, p1, s0);
            float y0 = __shfl_sync(0xffffffffu, p0, s1);
            float y1 = __shfl_sync(0xffffffffu, p1, s1);
            float z0 = __shfl_sync(0xffffffffu, p2, s0);
            float z1 = __shfl_sync(0xffffffffu, p3, s0);
            float u0 = __shfl_sync(0xffffffffu, p2, s1);
            float u1 = __shfl_sync(0xffffffffu, p3, s1);
            uint32_t a0 = f2tf32(odd ? x1 : x0);
            uint32_t a1 = f2tf32(odd ? z1 : z0);
            uint32_t a2 = f2tf32(odd ? y1 : y0);
            uint32_t a3 = f2tf32(odd ? u1 : u0);
#pragma unroll
            for (int nd = 0; nd < 8; nd++) {
                uint32_t b0 = __float_as_uint(Vs[ks * 8 + t][nd * 8 + g]);
                uint32_t b1 = __float_as_uint(Vs[ks * 8 + t + 4][nd * 8 + g]);
                mma_tf32(oa[nd], a0, a1, a2, a3, b0, b1);
            }
        }
    }

    // ---- normalize + write (tf32-rounded for the Wo GEMM) ----
    const float il0 = 1.0f / l0, il1 = 1.0f / l1;
    const int qrow = q0 + w * 16 + g;
    float* yp0 = g_Y + (size_t)(bb * T_ + qrow) * D_ + h * HD_;
    float* yp1 = yp0 + (size_t)8 * D_;
#pragma unroll
    for (int nd = 0; nd < 8; nd++) {
        const int col = nd * 8 + 2 * t;
        *(float2*)(yp0 + col) = make_float2(tf32r(oa[nd][0] * il0), tf32r(oa[nd][1] * il0));
        *(float2*)(yp1 + col) = make_float2(tf32r(oa[nd][2] * il1), tf32r(oa[nd][3] * il1));
    }
}

// ---------------------------------------------------------------------------
extern "C" void kernel_launch(void* const* d_in, const int* in_sizes, int n_in,
                              void* d_out, int out_size)
{
    const float* x  = (const float*)d_in[0];
    const float* Wq = (const float*)d_in[1];
    const float* Wk = (const float*)d_in[2];
    const float* Wv = (const float*)d_in[3];
    const float* Wo = (const float*)d_in[4];
    float* out = (float*)d_out;

    float *Q, *K, *V, *Y, *xr, *Wqr, *Wkr, *Wvr, *Wor;
    cudaGetSymbolAddress((void**)&Q, g_Q);
    cudaGetSymbolAddress((void**)&K, g_K);
    cudaGetSymbolAddress((void**)&V, g_V);
    cudaGetSymbolAddress((void**)&Y, g_Y);
    cudaGetSymbolAddress((void**)&xr, g_xr);
    cudaGetSymbolAddress((void**)&Wqr, g_Wqr);
    cudaGetSymbolAddress((void**)&Wkr, g_Wkr);
    cudaGetSymbolAddress((void**)&Wvr, g_Wvr);
    cudaGetSymbolAddress((void**)&Wor, g_Wor);

    // tf32 pre-rounding of GEMM operands
    round4_kernel<<<(MROWS * D_ / 4 + 255) / 256, 256>>>(x, xr, MROWS * D_ / 4);
    round4_kernel<<<(D_ * D_ / 4 + 255) / 256, 256>>>(Wq, Wqr, D_ * D_ / 4);
    round4_kernel<<<(D_ * KV_ / 4 + 255) / 256, 256>>>(Wk, Wkr, D_ * KV_ / 4);
    round4_kernel<<<(D_ * KV_ / 4 + 255) / 256, 256>>>(Wv, Wvr, D_ * KV_ / 4);
    round4_kernel<<<(D_ * D_ / 4 + 255) / 256, 256>>>(Wo, Wor, D_ * D_ / 4);

    // Projections (tf32 tensor cores, cp.async double-buffered)
    gemm_tf32_db<<<dim3(D_ / 128, MROWS / 128), 256>>>(xr, Wqr, Q, MROWS, D_, D_);
    gemm_tf32_db<<<dim3(KV_ / 128, MROWS / 128), 256>>>(xr, Wkr, K, MROWS, KV_, D_);
    gemm_tf32_db<<<dim3(KV_ / 128, MROWS / 128), 256>>>(xr, Wvr, V, MROWS, KV_, D_);

    // RoPE (+ q pre-scale, + k norm, + tf32 rounding of Q/K/V)
    rope_q_kernel<<<MROWS, NH_ * 32>>>();
    rope_k_kernel<<<MROWS, NKV_ * 32>>>();

    // Attention (tensor cores)
    flash_mma_kernel<<<dim3(T_ / 64, B_ * NH_), 128>>>();

    // Output projection
    gemm_tf32_db<<<dim3(D_ / 128, MROWS / 128), 256>>>(Y, Wor, out, MROWS, D_, D_);
}